// round 13
// baseline (speedup 1.0000x reference)
#include <cuda_runtime.h>
#include <cuda_fp16.h>
#include <cstdint>

// Problem constants (fixed by the dataset)
#define NNODES 50000
#define NEDGES 400000
#define FIN    128
#define HID    64
#define H1DIM  512                 // 8 heads * 64
#define NEG_SLOPE 0.2f

// ------------------------- scratch (static device memory) -------------------
__device__ __align__(128) __half g_xh[(size_t)NNODES * FIN];    // fp16 x
__device__ __align__(128) __half g_w1h[(size_t)FIN * H1DIM];    // fp16 W1
__device__ __align__(128) __half g_w2h[(size_t)H1DIM * HID];    // fp16 W2

__device__ __align__(128) __half g_h1h[(size_t)NNODES * H1DIM];   // x@W1
__device__ __align__(128) __half g_out1h[(size_t)NNODES * H1DIM]; // relu(agg1+b1)
__device__ float  g_alsrc1[(size_t)NNODES * 8];
__device__ float  g_aldst1[(size_t)NNODES * 8];

__device__ __align__(128) __half g_h2h[(size_t)NNODES * HID];     // layer2 features
__device__ float  g_alsrc2[NNODES];
__device__ float  g_aldst2[NNODES];

// CSR (dst-sorted incoming edges, self-loops excluded)
__device__ int g_cnt[NNODES];
__device__ int g_ptr[NNODES + 1];
__device__ int g_fill[NNODES];
__device__ int g_csrc[NEDGES];

// ------------------------- helpers ------------------------------------------
__device__ __forceinline__ void mma_f16(float d[4], const uint32_t a[4], const uint32_t b[2]) {
    asm volatile(
        "mma.sync.aligned.m16n8k16.row.col.f32.f16.f16.f32 "
        "{%0,%1,%2,%3}, {%4,%5,%6,%7}, {%8,%9}, {%0,%1,%2,%3};"
        : "+f"(d[0]), "+f"(d[1]), "+f"(d[2]), "+f"(d[3])
        : "r"(a[0]), "r"(a[1]), "r"(a[2]), "r"(a[3]), "r"(b[0]), "r"(b[1]));
}

__device__ __forceinline__ void ldsm_x4(uint32_t r[4], uint32_t addr) {
    asm volatile("ldmatrix.sync.aligned.m8n8.x4.shared.b16 {%0,%1,%2,%3}, [%4];"
                 : "=r"(r[0]), "=r"(r[1]), "=r"(r[2]), "=r"(r[3]) : "r"(addr));
}

__device__ __forceinline__ void ldsm_x2_trans(uint32_t r[2], uint32_t addr) {
    asm volatile("ldmatrix.sync.aligned.m8n8.x2.trans.shared.b16 {%0,%1}, [%2];"
                 : "=r"(r[0]), "=r"(r[1]) : "r"(addr));
}

__device__ __forceinline__ void cp_async16(uint32_t dst, const void* src, bool pred) {
    asm volatile("cp.async.cg.shared.global [%0], [%1], 16, %2;"
                 :: "r"(dst), "l"(src), "r"(pred ? 16 : 0));
}
__device__ __forceinline__ void cp_commit() {
    asm volatile("cp.async.commit_group;");
}
template<int W> __device__ __forceinline__ void cp_wait() {
    asm volatile("cp.async.wait_group %0;" :: "n"(W));
}

__device__ __forceinline__ float leaky_exp(float t) {
    t = (t > 0.f) ? t : NEG_SLOPE * t;
    return __expf(t);
}

// ------------------------- input fp16 conversion (one pass) ------------------
__global__ void cvt_inputs_kernel(const float* __restrict__ x,
                                  const float* __restrict__ W1,
                                  const float* __restrict__ W2)
{
    const int nx  = NNODES * FIN / 4;
    const int nw1 = FIN * H1DIM / 4;
    const int nw2 = H1DIM * HID / 4;
    int i = blockIdx.x * blockDim.x + threadIdx.x;
    int stride = gridDim.x * blockDim.x;
    for (int j = i; j < nx + nw1 + nw2; j += stride) {
        const float4* src;
        __half2* dst;
        int off;
        if (j < nx)            { src = (const float4*)x;  dst = (__half2*)g_xh;  off = j; }
        else if (j < nx + nw1) { src = (const float4*)W1; dst = (__half2*)g_w1h; off = j - nx; }
        else                   { src = (const float4*)W2; dst = (__half2*)g_w2h; off = j - nx - nw1; }
        float4 v = src[off];
        dst[off * 2]     = __floats2half2_rn(v.x, v.y);
        dst[off * 2 + 1] = __floats2half2_rn(v.z, v.w);
    }
}

// ------------------------- zero + CSR build ----------------------------------
__global__ void zero_cnt_kernel() {
    int i = blockIdx.x * blockDim.x + threadIdx.x;
    if (i < NNODES) g_cnt[i] = 0;
}

__global__ void hist_kernel(const int* __restrict__ ei) {
    int e = blockIdx.x * blockDim.x + threadIdx.x;
    if (e >= NEDGES) return;
    atomicAdd(&g_cnt[ei[NEDGES + e]], 1);
}

__global__ void scan_kernel() {
    __shared__ int sums[1024];
    const int T = 1024;
    const int tid = threadIdx.x;
    const int CH = (NNODES + T - 1) / T;
    const int base = tid * CH;
    int s = 0;
    for (int i = 0; i < CH; i++) {
        int idx = base + i;
        if (idx < NNODES) s += g_cnt[idx];
    }
    sums[tid] = s;
    __syncthreads();
    for (int off = 1; off < T; off <<= 1) {
        int v = (tid >= off) ? sums[tid - off] : 0;
        __syncthreads();
        sums[tid] += v;
        __syncthreads();
    }
    int run = (tid == 0) ? 0 : sums[tid - 1];
    for (int i = 0; i < CH; i++) {
        int idx = base + i;
        if (idx < NNODES) {
            g_ptr[idx] = run;
            g_fill[idx] = run;
            run += g_cnt[idx];
        }
    }
    if (tid == T - 1) g_ptr[NNODES] = run;
}

__global__ void fill_kernel(const int* __restrict__ ei) {
    int e = blockIdx.x * blockDim.x + threadIdx.x;
    if (e >= NEDGES) return;
    int s = ei[e];
    int d = ei[NEDGES + e];
    int pos = atomicAdd(&g_fill[d], 1);
    g_csrc[pos] = s;
}

// ------------------------- FP16 GEMM: cp.async 2-stage + ldmatrix + fused dots
// (unchanged from R12)
template<int BM, int BN, int BK, int WM, int WN, int HEADS, int K, int N>
__global__ __launch_bounds__(256)
void gemm_f16_att(int M,
                  const __half* __restrict__ A,
                  const __half* __restrict__ B,
                  const float* __restrict__ a_src,
                  const float* __restrict__ a_dst,
                  __half* __restrict__ Ch,
                  float* __restrict__ alsrc,
                  float* __restrict__ aldst)
{
    constexpr int WARPS_N = BN / WN;
    constexpr int MT = WM / 16;
    constexpr int NT = WN / 8;
    constexpr int ASS = BK + 8;
    constexpr int BSS = BN + 8;
    constexpr int HPB = BN / 64;
    constexpr int NK  = K / BK;
    constexpr int A_CP = BM * BK / (8 * 256);
    constexpr int B_CP = BK * BN / (8 * 256);
    constexpr uint32_t ASTAGE = BM * ASS * 2;
    constexpr uint32_t BSTAGE = BK * BSS * 2;

    __shared__ __half As[2][BM * ASS];
    __shared__ __half Bs[2][BK * BSS];
    __shared__ float s_as[BM * HPB];
    __shared__ float s_ad[BM * HPB];

    const int tid  = threadIdx.x;
    const int lane = tid & 31;
    const int warp = tid >> 5;
    const int block_row = blockIdx.y * BM;
    const int block_col = blockIdx.x * BN;
    const int wm = (warp / WARPS_N) * WM;
    const int wn = (warp % WARPS_N) * WN;
    const int g   = lane >> 2;
    const int tig = lane & 3;

    const uint32_t as0 = (uint32_t)__cvta_generic_to_shared(&As[0][0]);
    const uint32_t bs0 = (uint32_t)__cvta_generic_to_shared(&Bs[0][0]);

    const uint32_t a_lds_off = ((uint32_t)(wm + (lane & 15)) * ASS + (uint32_t)(lane >> 4) * 8) * 2;
    const uint32_t b_lds_off = ((uint32_t)(lane & 15) * BSS + (uint32_t)wn) * 2;

    const int a_r0 = tid / (BK / 8);
    const int a_u0 = tid % (BK / 8);
    const int b_r0 = tid / (BN / 8);
    const int b_u0 = tid % (BN / 8);

    for (int i = tid; i < BM * HPB; i += 256) { s_as[i] = 0.f; s_ad[i] = 0.f; }

    float acc[MT][NT][4];
#pragma unroll
    for (int mt = 0; mt < MT; mt++)
#pragma unroll
        for (int nt = 0; nt < NT; nt++)
#pragma unroll
            for (int j = 0; j < 4; j++) acc[mt][nt][j] = 0.f;

    auto issue = [&](int kt, int st) {
        int k0 = kt * BK;
#pragma unroll
        for (int i = 0; i < A_CP; i++) {
            int ar = a_r0 + i * (256 / (BK / 8));
            int grow = block_row + ar;
            uint32_t dst = as0 + st * ASTAGE + ((uint32_t)ar * ASS + (uint32_t)a_u0 * 8) * 2;
            cp_async16(dst, A + (size_t)grow * K + k0 + a_u0 * 8, grow < M);
        }
#pragma unroll
        for (int i = 0; i < B_CP; i++) {
            int br = b_r0 + i * (256 / (BN / 8));
            uint32_t dst = bs0 + st * BSTAGE + ((uint32_t)br * BSS + (uint32_t)b_u0 * 8) * 2;
            cp_async16(dst, B + (size_t)(k0 + br) * N + block_col + b_u0 * 8, true);
        }
    };

    issue(0, 0);
    cp_commit();

    for (int kt = 0; kt < NK; kt++) {
        int st = kt & 1;
        if (kt + 1 < NK) {
            issue(kt + 1, (kt + 1) & 1);
            cp_commit();
            cp_wait<1>();
        } else {
            cp_wait<0>();
        }
        __syncthreads();

        const uint32_t a_base = as0 + st * ASTAGE + a_lds_off;
        const uint32_t b_base = bs0 + st * BSTAGE + b_lds_off;
#pragma unroll
        for (int ks = 0; ks < BK / 16; ks++) {
            uint32_t af[MT][4], bf[NT][2];
#pragma unroll
            for (int mt = 0; mt < MT; mt++)
                ldsm_x4(af[mt], a_base + (uint32_t)(mt * 16 * ASS + ks * 16) * 2);
#pragma unroll
            for (int nt = 0; nt < NT; nt++)
                ldsm_x2_trans(bf[nt], b_base + (uint32_t)(ks * 16 * BSS + nt * 8) * 2);
#pragma unroll
            for (int mt = 0; mt < MT; mt++)
#pragma unroll
                for (int nt = 0; nt < NT; nt++)
                    mma_f16(acc[mt][nt], af[mt], bf[nt]);
        }
        __syncthreads();
    }

    const int head = (block_col + wn) >> 6;
    const int lhead = wn >> 6;
    float2 asv[NT], adv[NT];
#pragma unroll
    for (int nt = 0; nt < NT; nt++) {
        int ci = (block_col + wn + nt * 8 + 2 * tig) & 63;
        asv[nt] = *(const float2*)&a_src[head * HID + ci];
        adv[nt] = *(const float2*)&a_dst[head * HID + ci];
    }

#pragma unroll
    for (int mt = 0; mt < MT; mt++) {
        int r0 = block_row + wm + mt * 16 + g;
        int r1 = r0 + 8;
        float ss0 = 0.f, sd0 = 0.f, ss1 = 0.f, sd1 = 0.f;
#pragma unroll
        for (int nt = 0; nt < NT; nt++) {
            const float* c = acc[mt][nt];
            int col = block_col + wn + nt * 8 + 2 * tig;
            if (r0 < M) *(__half2*)&Ch[(size_t)r0 * N + col] = __floats2half2_rn(c[0], c[1]);
            if (r1 < M) *(__half2*)&Ch[(size_t)r1 * N + col] = __floats2half2_rn(c[2], c[3]);
            ss0 += c[0] * asv[nt].x + c[1] * asv[nt].y;
            sd0 += c[0] * adv[nt].x + c[1] * adv[nt].y;
            ss1 += c[2] * asv[nt].x + c[3] * asv[nt].y;
            sd1 += c[2] * adv[nt].x + c[3] * adv[nt].y;
        }
#pragma unroll
        for (int o = 1; o < 4; o <<= 1) {
            ss0 += __shfl_xor_sync(0xffffffffu, ss0, o);
            sd0 += __shfl_xor_sync(0xffffffffu, sd0, o);
            ss1 += __shfl_xor_sync(0xffffffffu, ss1, o);
            sd1 += __shfl_xor_sync(0xffffffffu, sd1, o);
        }
        if (tig == 0) {
            int lr0 = wm + mt * 16 + g;
            atomicAdd(&s_as[lr0 * HPB + lhead], ss0);
            atomicAdd(&s_ad[lr0 * HPB + lhead], sd0);
            atomicAdd(&s_as[(lr0 + 8) * HPB + lhead], ss1);
            atomicAdd(&s_ad[(lr0 + 8) * HPB + lhead], sd1);
        }
    }
    __syncthreads();
    for (int i = tid; i < BM * HPB; i += 256) {
        int lrow = i / HPB;
        int lh   = i % HPB;
        int grow = block_row + lrow;
        if (grow < M) {
            int gh = (block_col >> 6) + lh;
            alsrc[(size_t)grow * HEADS + gh] = s_as[i];
            aldst[(size_t)grow * HEADS + gh] = s_ad[i];
        }
    }
}

// ------------------------- layer1 aggregation (2 warps per dst node) ---------
// Warp-batched CSR indices via shfl + 4-edge load batching: breaks the serial
// csrc->feature dependent chain (in-order issue blocked MLP at ~1; now ~8).
// Invalid tail slots reuse edge 0's index with weight 0 (safe address).
__global__ __launch_bounds__(256)
void agg1_kernel(const float* __restrict__ b1)
{
    int gw   = (blockIdx.x * blockDim.x + threadIdx.x) >> 5;
    int d    = gw >> 1;
    int half = gw & 1;
    int lane = threadIdx.x & 31;
    if (d >= NNODES) return;
    const int colbase = half * 256 + lane * 8;
    const int head = colbase >> 6;

    const float adst = g_aldst1[(size_t)d * 8 + head];

    float acc[8];
    float den;
    // self-loop
    {
        float ex = leaky_exp(g_alsrc1[(size_t)d * 8 + head] + adst);
        den = ex;
        uint4 r = *(const uint4*)(g_h1h + (size_t)d * H1DIM + colbase);
        const __half2* a = (const __half2*)&r;
#pragma unroll
        for (int i = 0; i < 4; i++) {
            float2 f = __half22float2(a[i]);
            acc[2*i]   = ex * f.x;
            acc[2*i+1] = ex * f.y;
        }
    }

    const int beg = g_ptr[d], end = g_ptr[d + 1];
    for (int j0 = beg; j0 < end; j0 += 32) {
        const int cn = min(32, end - j0);
        // one coalesced index load per 32 edges
        int sidx = g_csrc[j0 + (lane < cn ? lane : 0)];
        for (int t = 0; t < cn; t += 4) {
            // uniform source-lane shfl (cn uniform across warp)
            int l1 = (t + 1 < cn) ? t + 1 : t;
            int l2 = (t + 2 < cn) ? t + 2 : t;
            int l3 = (t + 3 < cn) ? t + 3 : t;
            int s0 = __shfl_sync(0xffffffffu, sidx, t);
            int s1 = __shfl_sync(0xffffffffu, sidx, l1);
            int s2 = __shfl_sync(0xffffffffu, sidx, l2);
            int s3 = __shfl_sync(0xffffffffu, sidx, l3);
            // batched independent loads (MLP ~8)
            float al0 = g_alsrc1[(size_t)s0 * 8 + head];
            float al1 = g_alsrc1[(size_t)s1 * 8 + head];
            float al2 = g_alsrc1[(size_t)s2 * 8 + head];
            float al3 = g_alsrc1[(size_t)s3 * 8 + head];
            uint4 r0 = *(const uint4*)(g_h1h + (size_t)s0 * H1DIM + colbase);
            uint4 r1 = *(const uint4*)(g_h1h + (size_t)s1 * H1DIM + colbase);
            uint4 r2 = *(const uint4*)(g_h1h + (size_t)s2 * H1DIM + colbase);
            uint4 r3 = *(const uint4*)(g_h1h + (size_t)s3 * H1DIM + colbase);
            float ex0 = leaky_exp(al0 + adst);
            float ex1 = (t + 1 < cn) ? leaky_exp(al1 + adst) : 0.f;
            float ex2 = (t + 2 < cn) ? leaky_exp(al2 + adst) : 0.f;
            float ex3 = (t + 3 < cn) ? leaky_exp(al3 + adst) : 0.f;
            den += (ex0 + ex1) + (ex2 + ex3);
            const __half2* p0 = (const __half2*)&r0;
            const __half2* p1 = (const __half2*)&r1;
            const __half2* p2 = (const __half2*)&r2;
            const __half2* p3 = (const __half2*)&r3;
#pragma unroll
            for (int i = 0; i < 4; i++) {
                float2 f0 = __half22float2(p0[i]);
                float2 f1 = __half22float2(p1[i]);
                float2 f2 = __half22float2(p2[i]);
                float2 f3 = __half22float2(p3[i]);
                acc[2*i]   += ex0 * f0.x + ex1 * f1.x + ex2 * f2.x + ex3 * f3.x;
                acc[2*i+1] += ex0 * f0.y + ex1 * f1.y + ex2 * f2.y + ex3 * f3.y;
            }
        }
    }

    // epilogue: divide, +bias, relu, fp16 store
    float inv = __frcp_rn(den);
    const float* bp = b1 + colbase;
    __half2* op = (__half2*)(g_out1h + (size_t)d * H1DIM + colbase);
#pragma unroll
    for (int i = 0; i < 4; i++) {
        float vx = fmaxf(acc[2*i]   * inv + bp[2*i],   0.f);
        float vy = fmaxf(acc[2*i+1] * inv + bp[2*i+1], 0.f);
        op[i] = __floats2half2_rn(vx, vy);
    }
}

// ------------------------- layer2 aggregation + final projection -------------
__global__ __launch_bounds__(256)
void agg2_final_kernel(const float* __restrict__ b2,
                       const float* __restrict__ Wc,
                       const float* __restrict__ bc,
                       float* __restrict__ out)
{
    int d    = (blockIdx.x * blockDim.x + threadIdx.x) >> 5;
    int lane = threadIdx.x & 31;
    if (d >= NNODES) return;
    const int c0 = lane * 2;

    const float adst = g_aldst2[d];

    float acc0, acc1, den;
    {
        float ex = leaky_exp(g_alsrc2[d] + adst);
        den = ex;
        float2 f = __half22float2(*(const __half2*)(g_h2h + (size_t)d * HID + c0));
        acc0 = ex * f.x;
        acc1 = ex * f.y;
    }

    const int beg = g_ptr[d], end = g_ptr[d + 1];
    for (int j = beg; j < end; j++) {
        int s = g_csrc[j];
        float ex = leaky_exp(g_alsrc2[s] + adst);
        den += ex;
        float2 f = __half22float2(*(const __half2*)(g_h2h + (size_t)s * HID + c0));
        acc0 += ex * f.x;
        acc1 += ex * f.y;
    }

    float inv = __frcp_rn(den);
    float v0 = fmaxf(acc0 * inv + b2[c0],     0.f) * Wc[c0];
    float v1 = fmaxf(acc1 * inv + b2[c0 + 1], 0.f) * Wc[c0 + 1];
    float r = v0 + v1;
#pragma unroll
    for (int o = 16; o; o >>= 1) r += __shfl_down_sync(0xffffffffu, r, o);
    if (lane == 0) out[d] = r + bc[0];
}

// ------------------------- host launcher (single stream) ----------------------
extern "C" void kernel_launch(void* const* d_in, const int* in_sizes, int n_in,
                              void* d_out, int out_size)
{
    const float* x      = (const float*)d_in[0];
    const int*   ei     = (const int*)d_in[1];     // int32 (JAX x64 disabled)
    const float* W1     = (const float*)d_in[2];
    const float* a_src1 = (const float*)d_in[3];
    const float* a_dst1 = (const float*)d_in[4];
    const float* b1     = (const float*)d_in[5];
    const float* W2     = (const float*)d_in[6];
    const float* a_src2 = (const float*)d_in[7];
    const float* a_dst2 = (const float*)d_in[8];
    const float* b2     = (const float*)d_in[9];
    const float* Wc     = (const float*)d_in[10];
    const float* bc     = (const float*)d_in[11];
    float* out = (float*)d_out;

    static __half *s_xh = nullptr, *s_w1h = nullptr, *s_w2h = nullptr,
                  *s_h1h = nullptr, *s_h2h = nullptr, *s_out1h = nullptr;
    static float *s_alsrc1 = nullptr, *s_aldst1 = nullptr,
                 *s_alsrc2 = nullptr, *s_aldst2 = nullptr;
    if (!s_xh) {  // address lookup only; no device work; capture-safe
        cudaGetSymbolAddress((void**)&s_xh,     g_xh);
        cudaGetSymbolAddress((void**)&s_w1h,    g_w1h);
        cudaGetSymbolAddress((void**)&s_w2h,    g_w2h);
        cudaGetSymbolAddress((void**)&s_h1h,    g_h1h);
        cudaGetSymbolAddress((void**)&s_h2h,    g_h2h);
        cudaGetSymbolAddress((void**)&s_out1h,  g_out1h);
        cudaGetSymbolAddress((void**)&s_alsrc1, g_alsrc1);
        cudaGetSymbolAddress((void**)&s_aldst1, g_aldst1);
        cudaGetSymbolAddress((void**)&s_alsrc2, g_alsrc2);
        cudaGetSymbolAddress((void**)&s_aldst2, g_aldst2);
    }

    // 1) zero CSR counters
    zero_cnt_kernel<<<(NNODES + 255) / 256, 256>>>();
    // 2) convert x/W1/W2 to fp16 (one pass)
    cvt_inputs_kernel<<<4096, 256>>>(x, W1, W2);
    // 3) CSR histogram
    hist_kernel<<<(NEDGES + 255) / 256, 256>>>(ei);
    // 4) GEMM1 (kept in ncu capture slot): h1 = xh @ W1h  [50000,128]x[128,512]
    {
        dim3 grid(H1DIM / 128, (NNODES + 127) / 128);
        gemm_f16_att<128, 128, 32, 64, 32, 8, FIN, H1DIM>
            <<<grid, 256>>>(NNODES, s_xh, s_w1h, a_src1, a_dst1,
                            s_h1h, s_alsrc1, s_aldst1);
    }
    // 5) CSR scan + fill
    scan_kernel<<<1, 1024>>>();
    fill_kernel<<<(NEDGES + 255) / 256, 256>>>(ei);

    // 6) layer1: fused edge softmax + aggregation + bias/relu (2 warps per node)
    agg1_kernel<<<(NNODES * 64 + 255) / 256, 256>>>(b1);

    // 7) GEMM2: h2 = out1h @ W2h  [50000,512]x[512,64]
    {
        dim3 grid(HID / 64, (NNODES + 127) / 128);
        gemm_f16_att<128, 64, 32, 32, 32, 1, H1DIM, HID>
            <<<grid, 256>>>(NNODES, s_out1h, s_w2h, a_src2, a_dst2,
                            s_h2h, s_alsrc2, s_aldst2);
    }
    // 8) layer2: fused edge softmax + aggregation + final projection
    agg2_final_kernel<<<(NNODES * 32 + 255) / 256, 256>>>(b2, Wc, bc, out);
}

// round 14
// speedup vs baseline: 1.0500x; 1.0500x over previous
#include <cuda_runtime.h>
#include <cuda_fp16.h>
#include <cstdint>

// Problem constants (fixed by the dataset)
#define NNODES 50000
#define NEDGES 400000
#define FIN    128
#define HID    64
#define H1DIM  512                 // 8 heads * 64
#define NEG_SLOPE 0.2f

// ------------------------- scratch (static device memory) -------------------
__device__ __align__(128) __half g_xh[(size_t)NNODES * FIN];    // fp16 x
__device__ __align__(128) __half g_w1h[(size_t)FIN * H1DIM];    // fp16 W1
__device__ __align__(128) __half g_w2h[(size_t)H1DIM * HID];    // fp16 W2

__device__ __align__(128) __half g_h1h[(size_t)NNODES * H1DIM];   // x@W1
__device__ __align__(128) __half g_out1h[(size_t)NNODES * H1DIM]; // relu(agg1+b1)
__device__ float  g_alsrc1[(size_t)NNODES * 8];
__device__ float  g_aldst1[(size_t)NNODES * 8];

__device__ __align__(128) __half g_h2h[(size_t)NNODES * HID];     // layer2 features
__device__ float  g_alsrc2[NNODES];
__device__ float  g_aldst2[NNODES];

// CSR (dst-sorted incoming edges, self-loops excluded)
__device__ int g_cnt[NNODES];
__device__ int g_ptr[NNODES + 1];
__device__ int g_fill[NNODES];
__device__ int g_csrc[NEDGES];

// ------------------------- helpers ------------------------------------------
__device__ __forceinline__ void mma_f16(float d[4], const uint32_t a[4], const uint32_t b[2]) {
    asm volatile(
        "mma.sync.aligned.m16n8k16.row.col.f32.f16.f16.f32 "
        "{%0,%1,%2,%3}, {%4,%5,%6,%7}, {%8,%9}, {%0,%1,%2,%3};"
        : "+f"(d[0]), "+f"(d[1]), "+f"(d[2]), "+f"(d[3])
        : "r"(a[0]), "r"(a[1]), "r"(a[2]), "r"(a[3]), "r"(b[0]), "r"(b[1]));
}

__device__ __forceinline__ void ldsm_x4(uint32_t r[4], uint32_t addr) {
    asm volatile("ldmatrix.sync.aligned.m8n8.x4.shared.b16 {%0,%1,%2,%3}, [%4];"
                 : "=r"(r[0]), "=r"(r[1]), "=r"(r[2]), "=r"(r[3]) : "r"(addr));
}

__device__ __forceinline__ void ldsm_x2_trans(uint32_t r[2], uint32_t addr) {
    asm volatile("ldmatrix.sync.aligned.m8n8.x2.trans.shared.b16 {%0,%1}, [%2];"
                 : "=r"(r[0]), "=r"(r[1]) : "r"(addr));
}

__device__ __forceinline__ void cp_async16(uint32_t dst, const void* src, bool pred) {
    asm volatile("cp.async.cg.shared.global [%0], [%1], 16, %2;"
                 :: "r"(dst), "l"(src), "r"(pred ? 16 : 0));
}
__device__ __forceinline__ void cp_commit() {
    asm volatile("cp.async.commit_group;");
}
template<int W> __device__ __forceinline__ void cp_wait() {
    asm volatile("cp.async.wait_group %0;" :: "n"(W));
}

__device__ __forceinline__ float leaky_exp(float t) {
    t = (t > 0.f) ? t : NEG_SLOPE * t;
    return __expf(t);
}

// ------------------------- input fp16 conversion (one pass) ------------------
__global__ void cvt_inputs_kernel(const float* __restrict__ x,
                                  const float* __restrict__ W1,
                                  const float* __restrict__ W2)
{
    const int nx  = NNODES * FIN / 4;
    const int nw1 = FIN * H1DIM / 4;
    const int nw2 = H1DIM * HID / 4;
    int i = blockIdx.x * blockDim.x + threadIdx.x;
    int stride = gridDim.x * blockDim.x;
    for (int j = i; j < nx + nw1 + nw2; j += stride) {
        const float4* src;
        __half2* dst;
        int off;
        if (j < nx)            { src = (const float4*)x;  dst = (__half2*)g_xh;  off = j; }
        else if (j < nx + nw1) { src = (const float4*)W1; dst = (__half2*)g_w1h; off = j - nx; }
        else                   { src = (const float4*)W2; dst = (__half2*)g_w2h; off = j - nx - nw1; }
        float4 v = src[off];
        dst[off * 2]     = __floats2half2_rn(v.x, v.y);
        dst[off * 2 + 1] = __floats2half2_rn(v.z, v.w);
    }
}

// ------------------------- zero + CSR build ----------------------------------
__global__ void zero_cnt_kernel() {
    int i = blockIdx.x * blockDim.x + threadIdx.x;
    if (i < NNODES) g_cnt[i] = 0;
}

__global__ void hist_kernel(const int* __restrict__ ei) {
    int e = blockIdx.x * blockDim.x + threadIdx.x;
    if (e >= NEDGES) return;
    atomicAdd(&g_cnt[ei[NEDGES + e]], 1);
}

__global__ void scan_kernel() {
    __shared__ int sums[1024];
    const int T = 1024;
    const int tid = threadIdx.x;
    const int CH = (NNODES + T - 1) / T;
    const int base = tid * CH;
    int s = 0;
    for (int i = 0; i < CH; i++) {
        int idx = base + i;
        if (idx < NNODES) s += g_cnt[idx];
    }
    sums[tid] = s;
    __syncthreads();
    for (int off = 1; off < T; off <<= 1) {
        int v = (tid >= off) ? sums[tid - off] : 0;
        __syncthreads();
        sums[tid] += v;
        __syncthreads();
    }
    int run = (tid == 0) ? 0 : sums[tid - 1];
    for (int i = 0; i < CH; i++) {
        int idx = base + i;
        if (idx < NNODES) {
            g_ptr[idx] = run;
            g_fill[idx] = run;
            run += g_cnt[idx];
        }
    }
    if (tid == T - 1) g_ptr[NNODES] = run;
}

__global__ void fill_kernel(const int* __restrict__ ei) {
    int e = blockIdx.x * blockDim.x + threadIdx.x;
    if (e >= NEDGES) return;
    int s = ei[e];
    int d = ei[NEDGES + e];
    int pos = atomicAdd(&g_fill[d], 1);
    g_csrc[pos] = s;
}

// ------------------------- FP16 GEMM: cp.async 3-stage + ldmatrix + fused dots
// C[M,N] = A[M,K] @ B[K,N], all operands fp16 in gmem.
// 3-stage ring: 2 tiles in flight; single top-of-loop barrier publishes tile kt
// and retires stage (kt-1) so issuing tile kt+2 into that stage is safe.
template<int BM, int BN, int BK, int WM, int WN, int HEADS, int K, int N>
__global__ __launch_bounds__(256)
void gemm_f16_att(int M,
                  const __half* __restrict__ A,
                  const __half* __restrict__ B,
                  const float* __restrict__ a_src,
                  const float* __restrict__ a_dst,
                  __half* __restrict__ Ch,
                  float* __restrict__ alsrc,
                  float* __restrict__ aldst)
{
    constexpr int WARPS_N = BN / WN;
    constexpr int MT = WM / 16;
    constexpr int NT = WN / 8;
    constexpr int ASS = BK + 8;
    constexpr int BSS = BN + 8;
    constexpr int HPB = BN / 64;
    constexpr int NK  = K / BK;
    constexpr int NSTAGE = 3;
    constexpr int A_CP = BM * BK / (8 * 256);
    constexpr int B_CP = BK * BN / (8 * 256);
    constexpr uint32_t ASTAGE = BM * ASS * 2;
    constexpr uint32_t BSTAGE = BK * BSS * 2;

    __shared__ __half As[NSTAGE][BM * ASS];
    __shared__ __half Bs[NSTAGE][BK * BSS];
    __shared__ float s_as[BM * HPB];
    __shared__ float s_ad[BM * HPB];

    const int tid  = threadIdx.x;
    const int lane = tid & 31;
    const int warp = tid >> 5;
    const int block_row = blockIdx.y * BM;
    const int block_col = blockIdx.x * BN;
    const int wm = (warp / WARPS_N) * WM;
    const int wn = (warp % WARPS_N) * WN;
    const int g   = lane >> 2;
    const int tig = lane & 3;

    const uint32_t as0 = (uint32_t)__cvta_generic_to_shared(&As[0][0]);
    const uint32_t bs0 = (uint32_t)__cvta_generic_to_shared(&Bs[0][0]);

    const uint32_t a_lds_off = ((uint32_t)(wm + (lane & 15)) * ASS + (uint32_t)(lane >> 4) * 8) * 2;
    const uint32_t b_lds_off = ((uint32_t)(lane & 15) * BSS + (uint32_t)wn) * 2;

    const int a_r0 = tid / (BK / 8);
    const int a_u0 = tid % (BK / 8);
    const int b_r0 = tid / (BN / 8);
    const int b_u0 = tid % (BN / 8);

    for (int i = tid; i < BM * HPB; i += 256) { s_as[i] = 0.f; s_ad[i] = 0.f; }

    float acc[MT][NT][4];
#pragma unroll
    for (int mt = 0; mt < MT; mt++)
#pragma unroll
        for (int nt = 0; nt < NT; nt++)
#pragma unroll
            for (int j = 0; j < 4; j++) acc[mt][nt][j] = 0.f;

    auto issue = [&](int kt, int st) {
        int k0 = kt * BK;
#pragma unroll
        for (int i = 0; i < A_CP; i++) {
            int ar = a_r0 + i * (256 / (BK / 8));
            int grow = block_row + ar;
            uint32_t dst = as0 + st * ASTAGE + ((uint32_t)ar * ASS + (uint32_t)a_u0 * 8) * 2;
            cp_async16(dst, A + (size_t)grow * K + k0 + a_u0 * 8, grow < M);
        }
#pragma unroll
        for (int i = 0; i < B_CP; i++) {
            int br = b_r0 + i * (256 / (BN / 8));
            uint32_t dst = bs0 + st * BSTAGE + ((uint32_t)br * BSS + (uint32_t)b_u0 * 8) * 2;
            cp_async16(dst, B + (size_t)(k0 + br) * N + block_col + b_u0 * 8, true);
        }
    };

    // prologue: 2 tiles in flight
    issue(0, 0);
    cp_commit();
    if (NK > 1) { issue(1, 1); cp_commit(); }

    for (int kt = 0; kt < NK; kt++) {
        int st = kt % NSTAGE;
        if (kt + 1 < NK) cp_wait<1>();   // tile kt landed (one younger pending)
        else             cp_wait<0>();   // last tile: drain all
        __syncthreads();                 // publish tile kt; retire stage (kt-1)
        if (kt + 2 < NK) {
            issue(kt + 2, (kt + 2) % NSTAGE);   // overwrites stage (kt-1)%3: safe
            cp_commit();
        }

        const uint32_t a_base = as0 + st * ASTAGE + a_lds_off;
        const uint32_t b_base = bs0 + st * BSTAGE + b_lds_off;
#pragma unroll
        for (int ks = 0; ks < BK / 16; ks++) {
            uint32_t af[MT][4], bf[NT][2];
#pragma unroll
            for (int mt = 0; mt < MT; mt++)
                ldsm_x4(af[mt], a_base + (uint32_t)(mt * 16 * ASS + ks * 16) * 2);
#pragma unroll
            for (int nt = 0; nt < NT; nt++)
                ldsm_x2_trans(bf[nt], b_base + (uint32_t)(ks * 16 * BSS + nt * 8) * 2);
#pragma unroll
            for (int mt = 0; mt < MT; mt++)
#pragma unroll
                for (int nt = 0; nt < NT; nt++)
                    mma_f16(acc[mt][nt], af[mt], bf[nt]);
        }
    }
    __syncthreads();

    // epilogue: fp16 store + fused attention dots (smem reduction)
    const int head = (block_col + wn) >> 6;
    const int lhead = wn >> 6;
    float2 asv[NT], adv[NT];
#pragma unroll
    for (int nt = 0; nt < NT; nt++) {
        int ci = (block_col + wn + nt * 8 + 2 * tig) & 63;
        asv[nt] = *(const float2*)&a_src[head * HID + ci];
        adv[nt] = *(const float2*)&a_dst[head * HID + ci];
    }

#pragma unroll
    for (int mt = 0; mt < MT; mt++) {
        int r0 = block_row + wm + mt * 16 + g;
        int r1 = r0 + 8;
        float ss0 = 0.f, sd0 = 0.f, ss1 = 0.f, sd1 = 0.f;
#pragma unroll
        for (int nt = 0; nt < NT; nt++) {
            const float* c = acc[mt][nt];
            int col = block_col + wn + nt * 8 + 2 * tig;
            if (r0 < M) *(__half2*)&Ch[(size_t)r0 * N + col] = __floats2half2_rn(c[0], c[1]);
            if (r1 < M) *(__half2*)&Ch[(size_t)r1 * N + col] = __floats2half2_rn(c[2], c[3]);
            ss0 += c[0] * asv[nt].x + c[1] * asv[nt].y;
            sd0 += c[0] * adv[nt].x + c[1] * adv[nt].y;
            ss1 += c[2] * asv[nt].x + c[3] * asv[nt].y;
            sd1 += c[2] * adv[nt].x + c[3] * adv[nt].y;
        }
#pragma unroll
        for (int o = 1; o < 4; o <<= 1) {
            ss0 += __shfl_xor_sync(0xffffffffu, ss0, o);
            sd0 += __shfl_xor_sync(0xffffffffu, sd0, o);
            ss1 += __shfl_xor_sync(0xffffffffu, ss1, o);
            sd1 += __shfl_xor_sync(0xffffffffu, sd1, o);
        }
        if (tig == 0) {
            int lr0 = wm + mt * 16 + g;
            atomicAdd(&s_as[lr0 * HPB + lhead], ss0);
            atomicAdd(&s_ad[lr0 * HPB + lhead], sd0);
            atomicAdd(&s_as[(lr0 + 8) * HPB + lhead], ss1);
            atomicAdd(&s_ad[(lr0 + 8) * HPB + lhead], sd1);
        }
    }
    __syncthreads();
    for (int i = tid; i < BM * HPB; i += 256) {
        int lrow = i / HPB;
        int lh   = i % HPB;
        int grow = block_row + lrow;
        if (grow < M) {
            int gh = (block_col >> 6) + lh;
            alsrc[(size_t)grow * HEADS + gh] = s_as[i];
            aldst[(size_t)grow * HEADS + gh] = s_ad[i];
        }
    }
}

// ------------------------- layer1 aggregation (2 warps per dst node) ---------
// (R12 plain form — known good)
__global__ __launch_bounds__(256)
void agg1_kernel(const float* __restrict__ b1)
{
    int gw   = (blockIdx.x * blockDim.x + threadIdx.x) >> 5;
    int d    = gw >> 1;
    int half = gw & 1;
    int lane = threadIdx.x & 31;
    if (d >= NNODES) return;
    const int colbase = half * 256 + lane * 8;
    const int head = colbase >> 6;

    const float adst = g_aldst1[(size_t)d * 8 + head];

    float acc[8];
    float den;
    {
        float ex = leaky_exp(g_alsrc1[(size_t)d * 8 + head] + adst);
        den = ex;
        uint4 r = *(const uint4*)(g_h1h + (size_t)d * H1DIM + colbase);
        const __half2* a = (const __half2*)&r;
#pragma unroll
        for (int i = 0; i < 4; i++) {
            float2 f = __half22float2(a[i]);
            acc[2*i]   = ex * f.x;
            acc[2*i+1] = ex * f.y;
        }
    }

    const int beg = g_ptr[d], end = g_ptr[d + 1];
    for (int j = beg; j < end; j++) {
        int s = g_csrc[j];
        float ex = leaky_exp(g_alsrc1[(size_t)s * 8 + head] + adst);
        den += ex;
        uint4 r = *(const uint4*)(g_h1h + (size_t)s * H1DIM + colbase);
        const __half2* a = (const __half2*)&r;
#pragma unroll
        for (int i = 0; i < 4; i++) {
            float2 f = __half22float2(a[i]);
            acc[2*i]   += ex * f.x;
            acc[2*i+1] += ex * f.y;
        }
    }

    float inv = __frcp_rn(den);
    const float* bp = b1 + colbase;
    __half2* op = (__half2*)(g_out1h + (size_t)d * H1DIM + colbase);
#pragma unroll
    for (int i = 0; i < 4; i++) {
        float vx = fmaxf(acc[2*i]   * inv + bp[2*i],   0.f);
        float vy = fmaxf(acc[2*i+1] * inv + bp[2*i+1], 0.f);
        op[i] = __floats2half2_rn(vx, vy);
    }
}

// ------------------------- layer2 aggregation + final projection -------------
__global__ __launch_bounds__(256)
void agg2_final_kernel(const float* __restrict__ b2,
                       const float* __restrict__ Wc,
                       const float* __restrict__ bc,
                       float* __restrict__ out)
{
    int d    = (blockIdx.x * blockDim.x + threadIdx.x) >> 5;
    int lane = threadIdx.x & 31;
    if (d >= NNODES) return;
    const int c0 = lane * 2;

    const float adst = g_aldst2[d];

    float acc0, acc1, den;
    {
        float ex = leaky_exp(g_alsrc2[d] + adst);
        den = ex;
        float2 f = __half22float2(*(const __half2*)(g_h2h + (size_t)d * HID + c0));
        acc0 = ex * f.x;
        acc1 = ex * f.y;
    }

    const int beg = g_ptr[d], end = g_ptr[d + 1];
    for (int j = beg; j < end; j++) {
        int s = g_csrc[j];
        float ex = leaky_exp(g_alsrc2[s] + adst);
        den += ex;
        float2 f = __half22float2(*(const __half2*)(g_h2h + (size_t)s * HID + c0));
        acc0 += ex * f.x;
        acc1 += ex * f.y;
    }

    float inv = __frcp_rn(den);
    float v0 = fmaxf(acc0 * inv + b2[c0],     0.f) * Wc[c0];
    float v1 = fmaxf(acc1 * inv + b2[c0 + 1], 0.f) * Wc[c0 + 1];
    float r = v0 + v1;
#pragma unroll
    for (int o = 16; o; o >>= 1) r += __shfl_down_sync(0xffffffffu, r, o);
    if (lane == 0) out[d] = r + bc[0];
}

// ------------------------- host launcher (single stream) ----------------------
extern "C" void kernel_launch(void* const* d_in, const int* in_sizes, int n_in,
                              void* d_out, int out_size)
{
    const float* x      = (const float*)d_in[0];
    const int*   ei     = (const int*)d_in[1];     // int32 (JAX x64 disabled)
    const float* W1     = (const float*)d_in[2];
    const float* a_src1 = (const float*)d_in[3];
    const float* a_dst1 = (const float*)d_in[4];
    const float* b1     = (const float*)d_in[5];
    const float* W2     = (const float*)d_in[6];
    const float* a_src2 = (const float*)d_in[7];
    const float* a_dst2 = (const float*)d_in[8];
    const float* b2     = (const float*)d_in[9];
    const float* Wc     = (const float*)d_in[10];
    const float* bc     = (const float*)d_in[11];
    float* out = (float*)d_out;

    static __half *s_xh = nullptr, *s_w1h = nullptr, *s_w2h = nullptr,
                  *s_h1h = nullptr, *s_h2h = nullptr, *s_out1h = nullptr;
    static float *s_alsrc1 = nullptr, *s_aldst1 = nullptr,
                 *s_alsrc2 = nullptr, *s_aldst2 = nullptr;
    if (!s_xh) {  // address lookup only; no device work; capture-safe
        cudaGetSymbolAddress((void**)&s_xh,     g_xh);
        cudaGetSymbolAddress((void**)&s_w1h,    g_w1h);
        cudaGetSymbolAddress((void**)&s_w2h,    g_w2h);
        cudaGetSymbolAddress((void**)&s_h1h,    g_h1h);
        cudaGetSymbolAddress((void**)&s_h2h,    g_h2h);
        cudaGetSymbolAddress((void**)&s_out1h,  g_out1h);
        cudaGetSymbolAddress((void**)&s_alsrc1, g_alsrc1);
        cudaGetSymbolAddress((void**)&s_aldst1, g_aldst1);
        cudaGetSymbolAddress((void**)&s_alsrc2, g_alsrc2);
        cudaGetSymbolAddress((void**)&s_aldst2, g_aldst2);
    }

    // 1) zero CSR counters
    zero_cnt_kernel<<<(NNODES + 255) / 256, 256>>>();
    // 2) convert x/W1/W2 to fp16 (one pass)
    cvt_inputs_kernel<<<4096, 256>>>(x, W1, W2);
    // 3) CSR histogram
    hist_kernel<<<(NEDGES + 255) / 256, 256>>>(ei);
    // 4) GEMM1 (kept in ncu capture slot): h1 = xh @ W1h  [50000,128]x[128,512]
    {
        dim3 grid(H1DIM / 128, (NNODES + 127) / 128);
        gemm_f16_att<128, 128, 32, 64, 32, 8, FIN, H1DIM>
            <<<grid, 256>>>(NNODES, s_xh, s_w1h, a_src1, a_dst1,
                            s_h1h, s_alsrc1, s_aldst1);
    }
    // 5) CSR scan + fill
    scan_kernel<<<1, 1024>>>();
    fill_kernel<<<(NEDGES + 255) / 256, 256>>>(ei);

    // 6) layer1: fused edge softmax + aggregation + bias/relu (2 warps per node)
    agg1_kernel<<<(NNODES * 64 + 255) / 256, 256>>>(b1);

    // 7) GEMM2: h2 = out1h @ W2h  [50000,512]x[512,64]
    {
        dim3 grid(HID / 64, (NNODES + 127) / 128);
        gemm_f16_att<128, 64, 32, 32, 32, 1, H1DIM, HID>
            <<<grid, 256>>>(NNODES, s_out1h, s_w2h, a_src2, a_dst2,
                            s_h2h, s_alsrc2, s_aldst2);
    }
    // 8) layer2: fused edge softmax + aggregation + final projection
    agg2_final_kernel<<<(NNODES * 32 + 255) / 256, 256>>>(b2, Wc, bc, out);
}

// round 15
// speedup vs baseline: 1.0707x; 1.0197x over previous
#include <cuda_runtime.h>
#include <cuda_fp16.h>
#include <cstdint>

// Problem constants (fixed by the dataset)
#define NNODES 50000
#define NEDGES 400000
#define FIN    128
#define HID    64
#define H1DIM  512                 // 8 heads * 64
#define NEG_SLOPE 0.2f

// ------------------------- scratch (static device memory) -------------------
__device__ __align__(128) __half g_xh[(size_t)NNODES * FIN];    // fp16 x
__device__ __align__(128) __half g_w1h[(size_t)FIN * H1DIM];    // fp16 W1
__device__ __align__(128) __half g_w2h[(size_t)H1DIM * HID];    // fp16 W2

__device__ __align__(128) __half g_h1h[(size_t)NNODES * H1DIM];   // x@W1
__device__ __align__(128) __half g_out1h[(size_t)NNODES * H1DIM]; // relu(agg1+b1)
__device__ float  g_alsrc1[(size_t)NNODES * 8];
__device__ float  g_aldst1[(size_t)NNODES * 8];

__device__ __align__(128) __half g_h2h[(size_t)NNODES * HID];     // layer2 features
__device__ float  g_alsrc2[NNODES];
__device__ float  g_aldst2[NNODES];

// CSR (dst-sorted incoming edges, self-loops excluded)
__device__ int g_cnt[NNODES];
__device__ int g_ptr[NNODES + 1];
__device__ int g_fill[NNODES];
__device__ int g_csrc[NEDGES];

// ------------------------- helpers ------------------------------------------
__device__ __forceinline__ void mma_f16(float d[4], const uint32_t a[4], const uint32_t b[2]) {
    asm volatile(
        "mma.sync.aligned.m16n8k16.row.col.f32.f16.f16.f32 "
        "{%0,%1,%2,%3}, {%4,%5,%6,%7}, {%8,%9}, {%0,%1,%2,%3};"
        : "+f"(d[0]), "+f"(d[1]), "+f"(d[2]), "+f"(d[3])
        : "r"(a[0]), "r"(a[1]), "r"(a[2]), "r"(a[3]), "r"(b[0]), "r"(b[1]));
}

__device__ __forceinline__ void ldsm_x4(uint32_t r[4], uint32_t addr) {
    asm volatile("ldmatrix.sync.aligned.m8n8.x4.shared.b16 {%0,%1,%2,%3}, [%4];"
                 : "=r"(r[0]), "=r"(r[1]), "=r"(r[2]), "=r"(r[3]) : "r"(addr));
}

__device__ __forceinline__ void ldsm_x2_trans(uint32_t r[2], uint32_t addr) {
    asm volatile("ldmatrix.sync.aligned.m8n8.x2.trans.shared.b16 {%0,%1}, [%2];"
                 : "=r"(r[0]), "=r"(r[1]) : "r"(addr));
}

__device__ __forceinline__ void cp_async16(uint32_t dst, const void* src, bool pred) {
    asm volatile("cp.async.cg.shared.global [%0], [%1], 16, %2;"
                 :: "r"(dst), "l"(src), "r"(pred ? 16 : 0));
}
__device__ __forceinline__ void cp_commit() {
    asm volatile("cp.async.commit_group;");
}
template<int W> __device__ __forceinline__ void cp_wait() {
    asm volatile("cp.async.wait_group %0;" :: "n"(W));
}

__device__ __forceinline__ float leaky_exp(float t) {
    t = (t > 0.f) ? t : NEG_SLOPE * t;
    return __expf(t);
}

// ------------------------- input fp16 conversion + cnt zero (one pass) -------
__global__ void cvt_inputs_kernel(const float* __restrict__ x,
                                  const float* __restrict__ W1,
                                  const float* __restrict__ W2)
{
    const int nx  = NNODES * FIN / 4;
    const int nw1 = FIN * H1DIM / 4;
    const int nw2 = H1DIM * HID / 4;
    int i = blockIdx.x * blockDim.x + threadIdx.x;
    int stride = gridDim.x * blockDim.x;
    for (int j = i; j < NNODES; j += stride) g_cnt[j] = 0;   // fused zero pass
    for (int j = i; j < nx + nw1 + nw2; j += stride) {
        const float4* src;
        __half2* dst;
        int off;
        if (j < nx)            { src = (const float4*)x;  dst = (__half2*)g_xh;  off = j; }
        else if (j < nx + nw1) { src = (const float4*)W1; dst = (__half2*)g_w1h; off = j - nx; }
        else                   { src = (const float4*)W2; dst = (__half2*)g_w2h; off = j - nx - nw1; }
        float4 v = src[off];
        dst[off * 2]     = __floats2half2_rn(v.x, v.y);
        dst[off * 2 + 1] = __floats2half2_rn(v.z, v.w);
    }
}

// ------------------------- CSR build ------------------------------------------
__global__ void hist_kernel(const int* __restrict__ ei) {
    int e = blockIdx.x * blockDim.x + threadIdx.x;
    if (e >= NEDGES) return;
    atomicAdd(&g_cnt[ei[NEDGES + e]], 1);
}

__global__ void scan_kernel() {
    __shared__ int sums[1024];
    const int T = 1024;
    const int tid = threadIdx.x;
    const int CH = (NNODES + T - 1) / T;
    const int base = tid * CH;
    int s = 0;
    for (int i = 0; i < CH; i++) {
        int idx = base + i;
        if (idx < NNODES) s += g_cnt[idx];
    }
    sums[tid] = s;
    __syncthreads();
    for (int off = 1; off < T; off <<= 1) {
        int v = (tid >= off) ? sums[tid - off] : 0;
        __syncthreads();
        sums[tid] += v;
        __syncthreads();
    }
    int run = (tid == 0) ? 0 : sums[tid - 1];
    for (int i = 0; i < CH; i++) {
        int idx = base + i;
        if (idx < NNODES) {
            g_ptr[idx] = run;
            g_fill[idx] = run;
            run += g_cnt[idx];
        }
    }
    if (tid == T - 1) g_ptr[NNODES] = run;
}

__global__ void fill_kernel(const int* __restrict__ ei) {
    int e = blockIdx.x * blockDim.x + threadIdx.x;
    if (e >= NEDGES) return;
    int s = ei[e];
    int d = ei[NEDGES + e];
    int pos = atomicAdd(&g_fill[d], 1);
    g_csrc[pos] = s;
}

// ------------------------- FP16 GEMM: cp.async pipeline + ldmatrix + dots -----
// C[M,N] = A[M,K] @ B[K,N], all fp16 in gmem. NSTAGE-deep smem ring.
// When NK <= NSTAGE the loop degenerates to fully-resident K (no mid-loop
// producers) — used for GEMM1 (K=128, BK=64, 2 tiles).
template<int BM, int BN, int BK, int WM, int WN, int HEADS, int NSTAGE, int K, int N>
__global__ __launch_bounds__(256)
void gemm_f16_att(int M,
                  const __half* __restrict__ A,
                  const __half* __restrict__ B,
                  const float* __restrict__ a_src,
                  const float* __restrict__ a_dst,
                  __half* __restrict__ Ch,
                  float* __restrict__ alsrc,
                  float* __restrict__ aldst)
{
    constexpr int WARPS_N = BN / WN;
    constexpr int MT = WM / 16;
    constexpr int NT = WN / 8;
    constexpr int ASS = BK + 8;
    constexpr int BSS = BN + 8;
    constexpr int HPB = BN / 64;
    constexpr int NK  = K / BK;
    constexpr int A_CP = BM * BK / (8 * 256);
    constexpr int B_CP = BK * BN / (8 * 256);
    constexpr uint32_t ASTAGE = BM * ASS * 2;
    constexpr uint32_t BSTAGE = BK * BSS * 2;

    __shared__ __half As[NSTAGE][BM * ASS];
    __shared__ __half Bs[NSTAGE][BK * BSS];
    __shared__ float s_as[BM * HPB];
    __shared__ float s_ad[BM * HPB];

    const int tid  = threadIdx.x;
    const int lane = tid & 31;
    const int warp = tid >> 5;
    const int block_row = blockIdx.y * BM;
    const int block_col = blockIdx.x * BN;
    const int wm = (warp / WARPS_N) * WM;
    const int wn = (warp % WARPS_N) * WN;
    const int g   = lane >> 2;
    const int tig = lane & 3;

    const uint32_t as0 = (uint32_t)__cvta_generic_to_shared(&As[0][0]);
    const uint32_t bs0 = (uint32_t)__cvta_generic_to_shared(&Bs[0][0]);

    const uint32_t a_lds_off = ((uint32_t)(wm + (lane & 15)) * ASS + (uint32_t)(lane >> 4) * 8) * 2;
    const uint32_t b_lds_off = ((uint32_t)(lane & 15) * BSS + (uint32_t)wn) * 2;

    const int a_r0 = tid / (BK / 8);
    const int a_u0 = tid % (BK / 8);
    const int b_r0 = tid / (BN / 8);
    const int b_u0 = tid % (BN / 8);

    for (int i = tid; i < BM * HPB; i += 256) { s_as[i] = 0.f; s_ad[i] = 0.f; }

    float acc[MT][NT][4];
#pragma unroll
    for (int mt = 0; mt < MT; mt++)
#pragma unroll
        for (int nt = 0; nt < NT; nt++)
#pragma unroll
            for (int j = 0; j < 4; j++) acc[mt][nt][j] = 0.f;

    auto issue = [&](int kt, int st) {
        int k0 = kt * BK;
#pragma unroll
        for (int i = 0; i < A_CP; i++) {
            int ar = a_r0 + i * (256 / (BK / 8));
            int grow = block_row + ar;
            uint32_t dst = as0 + st * ASTAGE + ((uint32_t)ar * ASS + (uint32_t)a_u0 * 8) * 2;
            cp_async16(dst, A + (size_t)grow * K + k0 + a_u0 * 8, grow < M);
        }
#pragma unroll
        for (int i = 0; i < B_CP; i++) {
            int br = b_r0 + i * (256 / (BN / 8));
            uint32_t dst = bs0 + st * BSTAGE + ((uint32_t)br * BSS + (uint32_t)b_u0 * 8) * 2;
            cp_async16(dst, B + (size_t)(k0 + br) * N + block_col + b_u0 * 8, true);
        }
    };

    // prologue: up to NSTAGE-ahead (or all NK tiles if resident)
    issue(0, 0);
    cp_commit();
    if (NK > 1) { issue(1, 1); cp_commit(); }

    for (int kt = 0; kt < NK; kt++) {
        int st = kt % NSTAGE;
        if (kt + 1 < NK) cp_wait<1>();   // tile kt landed (one younger pending)
        else             cp_wait<0>();
        __syncthreads();                 // publish tile kt; retire stage (kt-1)
        if (kt + 2 < NK) {
            issue(kt + 2, (kt + 2) % NSTAGE);
            cp_commit();
        }

        const uint32_t a_base = as0 + st * ASTAGE + a_lds_off;
        const uint32_t b_base = bs0 + st * BSTAGE + b_lds_off;
#pragma unroll
        for (int ks = 0; ks < BK / 16; ks++) {
            uint32_t af[MT][4], bf[NT][2];
#pragma unroll
            for (int mt = 0; mt < MT; mt++)
                ldsm_x4(af[mt], a_base + (uint32_t)(mt * 16 * ASS + ks * 16) * 2);
#pragma unroll
            for (int nt = 0; nt < NT; nt++)
                ldsm_x2_trans(bf[nt], b_base + (uint32_t)(ks * 16 * BSS + nt * 8) * 2);
#pragma unroll
            for (int mt = 0; mt < MT; mt++)
#pragma unroll
                for (int nt = 0; nt < NT; nt++)
                    mma_f16(acc[mt][nt], af[mt], bf[nt]);
        }
    }
    __syncthreads();

    // epilogue: fp16 store + fused attention dots (smem reduction)
    const int head = (block_col + wn) >> 6;
    const int lhead = wn >> 6;
    float2 asv[NT], adv[NT];
#pragma unroll
    for (int nt = 0; nt < NT; nt++) {
        int ci = (block_col + wn + nt * 8 + 2 * tig) & 63;
        asv[nt] = *(const float2*)&a_src[head * HID + ci];
        adv[nt] = *(const float2*)&a_dst[head * HID + ci];
    }

#pragma unroll
    for (int mt = 0; mt < MT; mt++) {
        int r0 = block_row + wm + mt * 16 + g;
        int r1 = r0 + 8;
        float ss0 = 0.f, sd0 = 0.f, ss1 = 0.f, sd1 = 0.f;
#pragma unroll
        for (int nt = 0; nt < NT; nt++) {
            const float* c = acc[mt][nt];
            int col = block_col + wn + nt * 8 + 2 * tig;
            if (r0 < M) *(__half2*)&Ch[(size_t)r0 * N + col] = __floats2half2_rn(c[0], c[1]);
            if (r1 < M) *(__half2*)&Ch[(size_t)r1 * N + col] = __floats2half2_rn(c[2], c[3]);
            ss0 += c[0] * asv[nt].x + c[1] * asv[nt].y;
            sd0 += c[0] * adv[nt].x + c[1] * adv[nt].y;
            ss1 += c[2] * asv[nt].x + c[3] * asv[nt].y;
            sd1 += c[2] * adv[nt].x + c[3] * adv[nt].y;
        }
#pragma unroll
        for (int o = 1; o < 4; o <<= 1) {
            ss0 += __shfl_xor_sync(0xffffffffu, ss0, o);
            sd0 += __shfl_xor_sync(0xffffffffu, sd0, o);
            ss1 += __shfl_xor_sync(0xffffffffu, ss1, o);
            sd1 += __shfl_xor_sync(0xffffffffu, sd1, o);
        }
        if (tig == 0) {
            int lr0 = wm + mt * 16 + g;
            atomicAdd(&s_as[lr0 * HPB + lhead], ss0);
            atomicAdd(&s_ad[lr0 * HPB + lhead], sd0);
            atomicAdd(&s_as[(lr0 + 8) * HPB + lhead], ss1);
            atomicAdd(&s_ad[(lr0 + 8) * HPB + lhead], sd1);
        }
    }
    __syncthreads();
    for (int i = tid; i < BM * HPB; i += 256) {
        int lrow = i / HPB;
        int lh   = i % HPB;
        int grow = block_row + lrow;
        if (grow < M) {
            int gh = (block_col >> 6) + lh;
            alsrc[(size_t)grow * HEADS + gh] = s_as[i];
            aldst[(size_t)grow * HEADS + gh] = s_ad[i];
        }
    }
}

// ------------------------- layer1 aggregation (2 warps per dst node) ---------
// (R12 plain form — known good)
__global__ __launch_bounds__(256)
void agg1_kernel(const float* __restrict__ b1)
{
    int gw   = (blockIdx.x * blockDim.x + threadIdx.x) >> 5;
    int d    = gw >> 1;
    int half = gw & 1;
    int lane = threadIdx.x & 31;
    if (d >= NNODES) return;
    const int colbase = half * 256 + lane * 8;
    const int head = colbase >> 6;

    const float adst = g_aldst1[(size_t)d * 8 + head];

    float acc[8];
    float den;
    {
        float ex = leaky_exp(g_alsrc1[(size_t)d * 8 + head] + adst);
        den = ex;
        uint4 r = *(const uint4*)(g_h1h + (size_t)d * H1DIM + colbase);
        const __half2* a = (const __half2*)&r;
#pragma unroll
        for (int i = 0; i < 4; i++) {
            float2 f = __half22float2(a[i]);
            acc[2*i]   = ex * f.x;
            acc[2*i+1] = ex * f.y;
        }
    }

    const int beg = g_ptr[d], end = g_ptr[d + 1];
    for (int j = beg; j < end; j++) {
        int s = g_csrc[j];
        float ex = leaky_exp(g_alsrc1[(size_t)s * 8 + head] + adst);
        den += ex;
        uint4 r = *(const uint4*)(g_h1h + (size_t)s * H1DIM + colbase);
        const __half2* a = (const __half2*)&r;
#pragma unroll
        for (int i = 0; i < 4; i++) {
            float2 f = __half22float2(a[i]);
            acc[2*i]   += ex * f.x;
            acc[2*i+1] += ex * f.y;
        }
    }

    float inv = __frcp_rn(den);
    const float* bp = b1 + colbase;
    __half2* op = (__half2*)(g_out1h + (size_t)d * H1DIM + colbase);
#pragma unroll
    for (int i = 0; i < 4; i++) {
        float vx = fmaxf(acc[2*i]   * inv + bp[2*i],   0.f);
        float vy = fmaxf(acc[2*i+1] * inv + bp[2*i+1], 0.f);
        op[i] = __floats2half2_rn(vx, vy);
    }
}

// ------------------------- layer2 aggregation + final projection -------------
__global__ __launch_bounds__(256)
void agg2_final_kernel(const float* __restrict__ b2,
                       const float* __restrict__ Wc,
                       const float* __restrict__ bc,
                       float* __restrict__ out)
{
    int d    = (blockIdx.x * blockDim.x + threadIdx.x) >> 5;
    int lane = threadIdx.x & 31;
    if (d >= NNODES) return;
    const int c0 = lane * 2;

    const float adst = g_aldst2[d];

    float acc0, acc1, den;
    {
        float ex = leaky_exp(g_alsrc2[d] + adst);
        den = ex;
        float2 f = __half22float2(*(const __half2*)(g_h2h + (size_t)d * HID + c0));
        acc0 = ex * f.x;
        acc1 = ex * f.y;
    }

    const int beg = g_ptr[d], end = g_ptr[d + 1];
    for (int j = beg; j < end; j++) {
        int s = g_csrc[j];
        float ex = leaky_exp(g_alsrc2[s] + adst);
        den += ex;
        float2 f = __half22float2(*(const __half2*)(g_h2h + (size_t)s * HID + c0));
        acc0 += ex * f.x;
        acc1 += ex * f.y;
    }

    float inv = __frcp_rn(den);
    float v0 = fmaxf(acc0 * inv + b2[c0],     0.f) * Wc[c0];
    float v1 = fmaxf(acc1 * inv + b2[c0 + 1], 0.f) * Wc[c0 + 1];
    float r = v0 + v1;
#pragma unroll
    for (int o = 16; o; o >>= 1) r += __shfl_down_sync(0xffffffffu, r, o);
    if (lane == 0) out[d] = r + bc[0];
}

// ------------------------- host launcher (single stream) ----------------------
extern "C" void kernel_launch(void* const* d_in, const int* in_sizes, int n_in,
                              void* d_out, int out_size)
{
    const float* x      = (const float*)d_in[0];
    const int*   ei     = (const int*)d_in[1];     // int32 (JAX x64 disabled)
    const float* W1     = (const float*)d_in[2];
    const float* a_src1 = (const float*)d_in[3];
    const float* a_dst1 = (const float*)d_in[4];
    const float* b1     = (const float*)d_in[5];
    const float* W2     = (const float*)d_in[6];
    const float* a_src2 = (const float*)d_in[7];
    const float* a_dst2 = (const float*)d_in[8];
    const float* b2     = (const float*)d_in[9];
    const float* Wc     = (const float*)d_in[10];
    const float* bc     = (const float*)d_in[11];
    float* out = (float*)d_out;

    static __half *s_xh = nullptr, *s_w1h = nullptr, *s_w2h = nullptr,
                  *s_h1h = nullptr, *s_h2h = nullptr, *s_out1h = nullptr;
    static float *s_alsrc1 = nullptr, *s_aldst1 = nullptr,
                 *s_alsrc2 = nullptr, *s_aldst2 = nullptr;
    if (!s_xh) {  // address lookup only; no device work; capture-safe
        cudaGetSymbolAddress((void**)&s_xh,     g_xh);
        cudaGetSymbolAddress((void**)&s_w1h,    g_w1h);
        cudaGetSymbolAddress((void**)&s_w2h,    g_w2h);
        cudaGetSymbolAddress((void**)&s_h1h,    g_h1h);
        cudaGetSymbolAddress((void**)&s_h2h,    g_h2h);
        cudaGetSymbolAddress((void**)&s_out1h,  g_out1h);
        cudaGetSymbolAddress((void**)&s_alsrc1, g_alsrc1);
        cudaGetSymbolAddress((void**)&s_aldst1, g_aldst1);
        cudaGetSymbolAddress((void**)&s_alsrc2, g_alsrc2);
        cudaGetSymbolAddress((void**)&s_aldst2, g_aldst2);
    }

    // 1) convert x/W1/W2 to fp16 + zero CSR counters (one pass)
    cvt_inputs_kernel<<<4096, 256>>>(x, W1, W2);
    // 2) CSR histogram
    hist_kernel<<<(NEDGES + 255) / 256, 256>>>(ei);
    // 3) CSR scan
    scan_kernel<<<1, 1024>>>();
    // 4) GEMM1 (profiled slot): h1 = xh @ W1h  [50000,128]x[128,512]
    //    K fully resident: BK=64, 2 stages = 2 tiles, no mid-loop producers.
    {
        dim3 grid(H1DIM / 128, (NNODES + 127) / 128);
        gemm_f16_att<128, 128, 64, 64, 32, 8, 2, FIN, H1DIM>
            <<<grid, 256>>>(NNODES, s_xh, s_w1h, a_src1, a_dst1,
                            s_h1h, s_alsrc1, s_aldst1);
    }
    // 5) CSR fill
    fill_kernel<<<(NEDGES + 255) / 256, 256>>>(ei);

    // 6) layer1: fused edge softmax + aggregation + bias/relu (2 warps per node)
    agg1_kernel<<<(NNODES * 64 + 255) / 256, 256>>>(b1);

    // 7) GEMM2: h2 = out1h @ W2h  [50000,512]x[512,64]  (3-stage pipeline)
    {
        dim3 grid(HID / 64, (NNODES + 127) / 128);
        gemm_f16_att<128, 64, 32, 32, 32, 1, 3, H1DIM, HID>
            <<<grid, 256>>>(NNODES, s_out1h, s_w2h, a_src2, a_dst2,
                            s_h2h, s_alsrc2, s_aldst2);
    }
    // 8) layer2: fused edge softmax + aggregation + final projection
    agg2_final_kernel<<<(NNODES * 32 + 255) / 256, 256>>>(b2, Wc, bc, out);
}